// round 12
// baseline (speedup 1.0000x reference)
#include <cuda_runtime.h>
#include <cstdint>

// Problem dims (fixed): pred [8,4,256,256] f32, target [8,256,256] i32,
// boundary_weight [8,1,256,256] f32, output: scalar f32.
#define BQ 8
#define HQ 256
#define WQ 256
#define HWQ (HQ * WQ)
#define NPIX (BQ * HWQ)
#define NBLK (BQ * HQ)                      // 2048 blocks in pass B
#define BIGD2 (1 << 28)

// __device__ globals only (harness-sanctioned).
// g_hd: per-pixel packed horizontal window distances, produced by pass A,
//       consumed by pass B (4 MB).  .x = d_cls0 | d_cls1<<16, .y = cls2|cls3.
// g_done zero at module load, restored to zero by the last pass-B block.
__device__ uint2    g_hd[NPIX];
__device__ float    g_partial[NBLK];
__device__ unsigned g_done;

// ---------------------------------------------------------------------------
// Pass A: horizontal window min per pixel, once per image row.
// Grid: 2048 blocks (one per (b,i)), 256 threads (one per column).
// For each pixel: min dj^2 over columns j-3..j+3 for each of the 4 classes
// (64 = not present in the window). Bitplanes via ballot, 7-bit window via
// funnel shift, class masks via LOP3, distance via 128-entry smem LUT.
// ---------------------------------------------------------------------------
__global__ __launch_bounds__(256) void cwbl_hpass(const int* __restrict__ target) {
    const int bi = blockIdx.x;              // b*HQ + i
    const int j  = threadIdx.x;
    const int w  = j >> 5;
    const int l  = j & 31;

    __shared__ unsigned sw0[10], sw1[10];   // bitplane words + zero sentinels
    __shared__ unsigned slutA[128], slutB[128];

    if (j < 128) {
        const unsigned m = j;
        const unsigned d = (m & 0x08) ? 0u : (m & 0x14) ? 1u : (m & 0x22) ? 4u
                                           : (m & 0x41) ? 9u : 64u;
        slutA[m] = d;
        slutB[m] = d << 16;
    }
    if (j == 0) { sw0[0] = 0; sw1[0] = 0; sw0[9] = 0; sw1[9] = 0; }

    const int v = __ldg(&target[bi * WQ + j]);
    const unsigned m0 = __ballot_sync(0xffffffffu, v & 1);
    const unsigned m1 = __ballot_sync(0xffffffffu, v & 2);
    if (l == 0) { sw0[w + 1] = m0; sw1[w + 1] = m1; }
    __syncthreads();

    // 7-bit window centered on this column (bit k <-> dj = k-3)
    const unsigned p0 = sw0[w], c0 = sw0[w + 1], n0 = sw0[w + 2];
    const unsigned p1 = sw1[w], c1 = sw1[w + 1], n1 = sw1[w + 2];
    const unsigned w0 = (l < 3) ? __funnelshift_r(p0, c0, l + 29)
                                : __funnelshift_r(c0, n0, l - 3);
    const unsigned w1 = (l < 3) ? __funnelshift_r(p1, c1, l + 29)
                                : __funnelshift_r(c1, n1, l - 3);

    // column-validity mask (image edges)
    const int sl = max(0, 3 - j);
    const int sr = max(0, j - (WQ - 4));
    const unsigned vwin = ((0x7Fu << sl) & (0x7Fu >> sr)) & 0x7Fu;

    const unsigned mm0 = (~w0 & ~w1) & vwin;
    const unsigned mm1 = ( w0 & ~w1) & vwin;
    const unsigned mm2 = (~w0 &  w1) & vwin;
    const unsigned mm3 = ( w0 &  w1) & vwin;

    g_hd[bi * WQ + j] = make_uint2(slutA[mm0] + slutB[mm1],
                                   slutA[mm2] + slutB[mm3]);
}

// ---------------------------------------------------------------------------
// Pass B: vertical 7-tap DPX combine + softmax + weighted error + reduction.
// Grid: 2048 blocks (one per (b,i)), 256 threads (one per column).
//
// bd_c = min over di in [-3,3] of (hd[i+di][c] + di^2); certified exact when
// <= 15 (any pixel outside the 7x7 box has d2 >= 16; 16,17 are unreachable
// inside it). Uncertified (>16) pixels take the exact expanding-ring search.
// Unfound classes give dist 0, reproducing the reference's degenerate-class
// zeroing (absent class -> never found; full class -> no "other" found).
// ---------------------------------------------------------------------------
__global__ __launch_bounds__(256) void cwbl_vpass(
        const float* __restrict__ pred,
        const int*   __restrict__ target,
        const float* __restrict__ wgt,
        float*       __restrict__ out) {
    const int bi = blockIdx.x;              // b*HQ + i
    const int b  = bi >> 8;
    const int i  = bi & (HQ - 1);
    const int j  = threadIdx.x;
    const int w  = j >> 5;
    const int l  = j & 31;

    const int* tb   = target + b * HWQ;
    const int  base = i * WQ + j;

    __shared__ float ssq[20];
    __shared__ float sa[8];
    if (j < 20) ssq[j] = sqrtf((float)j);

    const int t = __ldg(&tb[base]);

    // --- vertical DPX combine over 7 packed rows (7 coalesced LDG.64) ---
    unsigned blo = 0x00FF00FFu, bhi = 0x00FF00FFu;
#pragma unroll
    for (int q = 0; q < 7; ++q) {
        const int ii  = i + q - 3;
        const bool rv = ((unsigned)ii < (unsigned)HQ);
        const int iic = min(HQ - 1, max(0, ii));
        const uint2 hv = __ldg(&g_hd[(b * HQ + iic) * WQ + j]);
        const unsigned dlo = rv ? hv.x : 0x00400040u;
        const unsigned dhi = rv ? hv.y : 0x00400040u;
        const int di = q - 3;
        const unsigned dd = (unsigned)(di * di) * 0x00010001u;  // compile-time
        blo = __viaddmin_u16x2(dlo, dd, blo);
        bhi = __viaddmin_u16x2(dhi, dd, bhi);
    }
    int bd0 = (int)(blo & 0xFFFFu), bd1 = (int)(blo >> 16);
    int bd2 = (int)(bhi & 0xFFFFu), bd3 = (int)(bhi >> 16);

    int mo = min(min((t == 0) ? BIGD2 : bd0, (t == 1) ? BIGD2 : bd1),
                 min((t == 2) ? BIGD2 : bd2, (t == 3) ? BIGD2 : bd3));
    int n1 = (t == 1) ? mo : bd1;
    int n2 = (t == 2) ? mo : bd2;
    int n3 = (t == 3) ? mo : bd3;

    // --- rare exact ring fallback (window certifies d2 <= 16) ---
    if (max(n1, max(n2, n3)) > 16) {
        bd0 = (bd0 > 18) ? BIGD2 : bd0;
        bd1 = (bd1 > 18) ? BIGD2 : bd1;
        bd2 = (bd2 > 18) ? BIGD2 : bd2;
        bd3 = (bd3 > 18) ? BIGD2 : bd3;
#pragma unroll 1
        for (int r = 4; r < 256; ++r) {
            int mo_ = BIGD2;
            if (t != 0) mo_ = min(mo_, bd0);
            if (t != 1) mo_ = min(mo_, bd1);
            if (t != 2) mo_ = min(mo_, bd2);
            if (t != 3) mo_ = min(mo_, bd3);
            int M = 0;
            M = max(M, (t == 1) ? mo_ : bd1);
            M = max(M, (t == 2) ? mo_ : bd2);
            M = max(M, (t == 3) ? mo_ : bd3);
            if (r * r >= M) break;

            const int r2   = r * r;
            const int itop = i - r;
            const int ibot = i + r;
            const bool okT = (itop >= 0);
            const bool okB = (ibot < HQ);
            const int* rowT = tb + itop * WQ;
            const int* rowB = tb + ibot * WQ;
#pragma unroll 1
            for (int dj = -r; dj <= r; ++dj) {
                const int jj = j + dj;
                if ((unsigned)jj >= (unsigned)WQ) continue;
                const int d2 = r2 + dj * dj;
                if (okT) {
                    const int v = __ldg(&rowT[jj]);
                    bd0 = min(bd0, (v == 0) ? d2 : BIGD2);
                    bd1 = min(bd1, (v == 1) ? d2 : BIGD2);
                    bd2 = min(bd2, (v == 2) ? d2 : BIGD2);
                    bd3 = min(bd3, (v == 3) ? d2 : BIGD2);
                }
                if (okB) {
                    const int v = __ldg(&rowB[jj]);
                    bd0 = min(bd0, (v == 0) ? d2 : BIGD2);
                    bd1 = min(bd1, (v == 1) ? d2 : BIGD2);
                    bd2 = min(bd2, (v == 2) ? d2 : BIGD2);
                    bd3 = min(bd3, (v == 3) ? d2 : BIGD2);
                }
            }
            const int jl = j - r;
            const int jr = j + r;
            const bool okL = (jl >= 0);
            const bool okR = (jr < WQ);
#pragma unroll 1
            for (int di = -r + 1; di <= r - 1; ++di) {
                const int ii = i + di;
                if ((unsigned)ii >= (unsigned)HQ) continue;
                const int d2  = di * di + r2;
                const int* row = tb + ii * WQ;
                if (okL) {
                    const int v = __ldg(&row[jl]);
                    bd0 = min(bd0, (v == 0) ? d2 : BIGD2);
                    bd1 = min(bd1, (v == 1) ? d2 : BIGD2);
                    bd2 = min(bd2, (v == 2) ? d2 : BIGD2);
                    bd3 = min(bd3, (v == 3) ? d2 : BIGD2);
                }
                if (okR) {
                    const int v = __ldg(&row[jr]);
                    bd0 = min(bd0, (v == 0) ? d2 : BIGD2);
                    bd1 = min(bd1, (v == 1) ? d2 : BIGD2);
                    bd2 = min(bd2, (v == 2) ? d2 : BIGD2);
                    bd3 = min(bd3, (v == 3) ? d2 : BIGD2);
                }
            }
        }
        mo = BIGD2;
        if (t != 0) mo = min(mo, bd0);
        if (t != 1) mo = min(mo, bd1);
        if (t != 2) mo = min(mo, bd2);
        if (t != 3) mo = min(mo, bd3);
        n1 = (t == 1) ? mo : bd1;
        n2 = (t == 2) ? mo : bd2;
        n3 = (t == 3) ? mo : bd3;
    }

    // --- distances: LUT for certified range, rare branch otherwise ---
    float d1f = ssq[min(n1, 19)];
    float d2f = ssq[min(n2, 19)];
    float d3f = ssq[min(n3, 19)];
    if (max(n1, max(n2, n3)) > 18) {            // ~never (warp-skipped)
        d1f = (n1 <= 18) ? d1f : ((n1 < BIGD2) ? sqrtf((float)n1) : 0.0f);
        d2f = (n2 <= 18) ? d2f : ((n2 < BIGD2) ? sqrtf((float)n2) : 0.0f);
        d3f = (n3 <= 18) ? d3f : ((n3 < BIGD2) ? sqrtf((float)n3) : 0.0f);
    }

    // --- softmax + weighted error ---
    const float* pb = pred + (size_t)b * 4 * HWQ;
    const float wv = __ldg(&wgt[b * HWQ + base]);
    const float x0 = __ldg(&pb[base]);
    const float x1 = __ldg(&pb[HWQ + base]);
    const float x2 = __ldg(&pb[2 * HWQ + base]);
    const float x3 = __ldg(&pb[3 * HWQ + base]);
    const float mx = fmaxf(fmaxf(x0, x1), fmaxf(x2, x3));
    const float e0 = __expf(x0 - mx);
    const float e1 = __expf(x1 - mx);
    const float e2 = __expf(x2 - mx);
    const float e3 = __expf(x3 - mx);
    const float rd = __fdividef(1.0f, e0 + e1 + e2 + e3);

    float acc = fabsf(e1 * rd - ((t == 1) ? 1.0f : 0.0f)) * d1f;
    acc      += fabsf(e2 * rd - ((t == 2) ? 1.0f : 0.0f)) * d2f;
    acc      += fabsf(e3 * rd - ((t == 3) ? 1.0f : 0.0f)) * d3f;
    acc      *= wv;

    // --- block reduction -> per-block partial (fixed order, no atomics) ---
#pragma unroll
    for (int o = 16; o > 0; o >>= 1)
        acc += __shfl_down_sync(0xffffffffu, acc, o);
    if (l == 0) sa[w] = acc;
    __syncthreads();
    if (j == 0) {
        float s = 0.0f;
#pragma unroll
        for (int k = 0; k < 8; ++k) s += sa[k];
        g_partial[bi] = s;
    }

    // --- last-block deterministic finalize ---
    __shared__ unsigned ticket;
    __threadfence();
    if (j == 0) ticket = atomicAdd(&g_done, 1u);
    __syncthreads();
    if (ticket == NBLK - 1) {
        __threadfence();
        __shared__ double sd[256];
        double s = 0.0;
        for (int k = j; k < NBLK; k += 256)
            s += (double)g_partial[k];              // fixed order
        sd[j] = s;
        __syncthreads();
#pragma unroll
        for (int st = 128; st > 0; st >>= 1) {
            if (j < st) sd[j] += sd[j + st];
            __syncthreads();
        }
        if (j == 0) {
            out[0] = (float)(sd[0] / (3.0 * (double)NPIX));
            g_done = 0;                             // restore invariant
        }
    }
}

// ---------------------------------------------------------------------------
extern "C" void kernel_launch(void* const* d_in, const int* in_sizes, int n_in,
                              void* d_out, int out_size) {
    const float* pred   = (const float*)d_in[0];
    const int*   target = (const int*)d_in[1];
    const float* wgt    = (const float*)d_in[2];
    float* out = (float*)d_out;
    (void)in_sizes; (void)n_in; (void)out_size;

    cwbl_hpass<<<NBLK, 256>>>(target);
    cwbl_vpass<<<NBLK, 256>>>(pred, target, wgt, out);
}